// round 9
// baseline (speedup 1.0000x reference)
#include <cuda_runtime.h>
#include <cstdint>

// x (8,3,1024,1024) f32 -> out (8,3,512,512) f32
// d_in: [0]=x, [1]=w0 (K0*512), [2]=fov0 (K0*512 i32)  -> dim2 (H, vertical)
//       [3]=w1 (K1*512), [4]=fov1 (K1*512 i32)         -> dim3 (W, horizontal)
//
// R9: SINGLE-WAVE persistent grid. 768 blocks, each handles 2 consecutive
// oh-tiles; all blocks resident at once (no 7.5%-full third wave, no wave
// transitions — the hidden cost behind R5-R8's flat ~34us).
// Registers cut via lazy accumulator init (acc[i] live only over its K-tap
// window: 16 live regs instead of 32) + __launch_bounds__(256,6).
// Phase 2: R8 aligned-LDS.128 fast path, weights/checks hoisted.

#define BC     24
#define IN_H   1024
#define IN_W   1024
#define OUT_H  512
#define OUT_W  512
#define G      8            // output rows per tile
#define PADW   16           // tile row padding (floats) on each side
#define TROW   (IN_W + 2 * PADW)

// ---------------------------------------------------------------------------
template<int K, int O>
__device__ __forceinline__
void hfast_rows(const float tile[G][TROW], int wstart,
                const float* __restrict__ wh,
                float* __restrict__ outp /* &out[bc][oh0][ow0] */)
{
    constexpr int NQ = (K + 8) / 4;
#pragma unroll
    for (int i = 0; i < G; ++i) {
        const float4* rp = reinterpret_cast<const float4*>(tile[i] + PADW) + wstart;
        float r[NQ * 4];
#pragma unroll
        for (int q = 0; q < NQ; ++q) {
            const float4 v = rp[q];
            r[4 * q + 0] = v.x; r[4 * q + 1] = v.y;
            r[4 * q + 2] = v.z; r[4 * q + 3] = v.w;
        }
        float a0 = 0.f, a1 = 0.f;
#pragma unroll
        for (int j = 0; j < K; ++j) {
            a0 += wh[j] * r[O + j];
            a1 += wh[j] * r[O + 2 + j];
        }
        float2 res; res.x = a0; res.y = a1;
        *reinterpret_cast<float2*>(outp + (size_t)i * OUT_W) = res;
    }
}

// ---------------------------------------------------------------------------
template<int K>
__global__ __launch_bounds__(256, 6)
void fused_stream_kernel(const float* __restrict__ x,
                         const float* __restrict__ w0,
                         const int*   __restrict__ fov0,
                         const float* __restrict__ w1,
                         const int*   __restrict__ fov1,
                         float*       __restrict__ out)
{
    __shared__ float tile[G][TROW];

    const int t  = threadIdx.x;                  // 0..255
    const int bc = blockIdx.y;

    const float4* xb = reinterpret_cast<const float4*>(x + (size_t)bc * IN_H * IN_W);

    // ---- hoisted horizontal setup (identical for both tiles) ---------------
    const int ow0 = 2 * t;
    const int s1  = fov1[256] - 512;             // reference interior column

    float wh[K];
#pragma unroll
    for (int j = 0; j < K; ++j) wh[j] = w1[j * OUT_W + 256];

    int hok = 1;
#pragma unroll
    for (int j = 0; j < K; ++j) {
        const int2   fv = *reinterpret_cast<const int2*>(fov1 + j * OUT_W + ow0);
        const float2 wv2 = *reinterpret_cast<const float2*>(w1  + j * OUT_W + ow0);
        hok &= (fv.x == s1 + 2 * ow0 + j) & (fv.y == s1 + 2 * ow0 + 2 + j);
        hok &= (wv2.x == wh[j]) & (wv2.y == wh[j]);
    }

    // ---- two consecutive oh-tiles per block ---------------------------------
#pragma unroll 1
    for (int half = 0; half < 2; ++half) {
        const int oh0 = (blockIdx.x * 2 + half) * G;

        // vertical regularity: fov0[j][oh0+i] == start + 2i + j, w0 oh-invar.
        // (__syncthreads_and is also the barrier protecting tile reuse)
        const int start = fov0[oh0];
        int flag = 1;
        if (t < K * G) {
            const int j  = t / G;
            const int i  = t % G;
            const int oh = oh0 + i;
            flag  = (fov0[j * OUT_H + oh] == start + 2 * i + j);
            flag &= (w0  [j * OUT_H + oh] == w0[j * OUT_H + oh0]);
        }
        const int regular = __syncthreads_and(flag);

        if (regular) {
            constexpr int NROWS = K + 2 * (G - 1);

            float wv[K];
#pragma unroll
            for (int j = 0; j < K; ++j) wv[j] = w0[j * OUT_H + oh0];

            float4 acc[G];
#pragma unroll
            for (int m = 0; m < NROWS; ++m) {
                const float4 v = xb[(size_t)(start + m) * (IN_W / 4) + t];
#pragma unroll
                for (int i = 0; i < G; ++i) {
                    const int j = m - 2 * i;
                    if (j == 0) {                 // lazy init: shortens live range
                        acc[i].x = wv[0] * v.x;
                        acc[i].y = wv[0] * v.y;
                        acc[i].z = wv[0] * v.z;
                        acc[i].w = wv[0] * v.w;
                    } else if (j > 0 && j < K) {
                        acc[i].x += wv[j] * v.x;
                        acc[i].y += wv[j] * v.y;
                        acc[i].z += wv[j] * v.z;
                        acc[i].w += wv[j] * v.w;
                    }
                }
                if (m >= K - 1 && ((m - (K - 1)) & 1) == 0) {
                    const int i = (m - (K - 1)) / 2;   // retire closed window
                    reinterpret_cast<float4*>(tile[i] + PADW)[t] = acc[i];
                }
            }
        } else {
            for (int i = 0; i < G; ++i) {
                const int oh = oh0 + i;
                float ax = 0.f, ay = 0.f, az = 0.f, aw = 0.f;
                for (int j = 0; j < K; ++j) {
                    const int   r = fov0[j * OUT_H + oh];
                    const float w = w0  [j * OUT_H + oh];
                    const float4 v = xb[(size_t)r * (IN_W / 4) + t];
                    ax += w * v.x; ay += w * v.y; az += w * v.z; aw += w * v.w;
                }
                float4 r4; r4.x = ax; r4.y = ay; r4.z = az; r4.w = aw;
                reinterpret_cast<float4*>(tile[i] + PADW)[t] = r4;
            }
        }
        __syncthreads();

        // ---------------- Phase 2: horizontal resample ----------------------
        float* outp = out + ((size_t)bc * OUT_H + oh0) * OUT_W + ow0;

        if (hok) {
            const int o      = s1 & 3;            // uniform across entire grid
            const int wstart = (s1 + 4 * t) >> 2;
            if      (o == 0) hfast_rows<K, 0>(tile, wstart, wh, outp);
            else if (o == 1) hfast_rows<K, 1>(tile, wstart, wh, outp);
            else if (o == 2) hfast_rows<K, 2>(tile, wstart, wh, outp);
            else             hfast_rows<K, 3>(tile, wstart, wh, outp);
        } else {
            for (int i = 0; i < G; ++i) {
                float b0 = 0.f, b1 = 0.f;
                for (int j = 0; j < K; ++j) {
                    b0 += w1[j * OUT_W + ow0]     * tile[i][PADW + fov1[j * OUT_W + ow0]];
                    b1 += w1[j * OUT_W + ow0 + 1] * tile[i][PADW + fov1[j * OUT_W + ow0 + 1]];
                }
                float2 res; res.x = b0; res.y = b1;
                *reinterpret_cast<float2*>(outp + (size_t)i * OUT_W) = res;
            }
        }
    }
}

// ---------------------------------------------------------------------------
// Fully generic fallback (runtime K0/K1), parity-split tile.
__global__ __launch_bounds__(256)
void fused_generic_kernel(const float* __restrict__ x,
                          const float* __restrict__ w0,
                          const int*   __restrict__ fov0,
                          const float* __restrict__ w1,
                          const int*   __restrict__ fov1,
                          float*       __restrict__ out,
                          int K0, int K1)
{
    __shared__ float tile[G][IN_W];
    const int t   = threadIdx.x;
    const int bc  = blockIdx.y;
    const int oh0 = blockIdx.x * G;
    const float4* xb = reinterpret_cast<const float4*>(x + (size_t)bc * IN_H * IN_W);

    for (int i = 0; i < G; ++i) {
        const int oh = oh0 + i;
        float ax = 0.f, ay = 0.f, az = 0.f, aw = 0.f;
        for (int j = 0; j < K0; ++j) {
            const int   r = fov0[j * OUT_H + oh];
            const float w = w0  [j * OUT_H + oh];
            const float4 v = xb[(size_t)r * (IN_W / 4) + t];
            ax += w * v.x; ay += w * v.y; az += w * v.z; aw += w * v.w;
        }
        float2 e; e.x = ax; e.y = az;
        float2 o; o.x = ay; o.y = aw;
        reinterpret_cast<float2*>(tile[i])[t]       = e;
        reinterpret_cast<float2*>(tile[i] + 512)[t] = o;
    }
    __syncthreads();

    float a0[G], a1[G];
#pragma unroll
    for (int i = 0; i < G; ++i) { a0[i] = 0.f; a1[i] = 0.f; }
    for (int j = 0; j < K1; ++j) {
        const float w_a = w1  [j * OUT_W + t];
        const float w_b = w1  [j * OUT_W + t + 256];
        const int   f_a = fov1[j * OUT_W + t];
        const int   f_b = fov1[j * OUT_W + t + 256];
        const int p_a = (f_a >> 1) + ((f_a & 1) << 9);
        const int p_b = (f_b >> 1) + ((f_b & 1) << 9);
#pragma unroll
        for (int i = 0; i < G; ++i) {
            a0[i] += w_a * tile[i][p_a];
            a1[i] += w_b * tile[i][p_b];
        }
    }
#pragma unroll
    for (int i = 0; i < G; ++i) {
        float* orow = out + ((size_t)bc * OUT_H + oh0 + i) * OUT_W;
        orow[t]       = a0[i];
        orow[t + 256] = a1[i];
    }
}

// ---------------------------------------------------------------------------

extern "C" void kernel_launch(void* const* d_in, const int* in_sizes, int n_in,
                              void* d_out, int out_size)
{
    const float* x    = (const float*)d_in[0];
    const float* w0   = (const float*)d_in[1];
    const int*   fov0 = (const int*)  d_in[2];
    const float* w1   = (const float*)d_in[3];
    const int*   fov1 = (const int*)  d_in[4];
    float*       out  = (float*)d_out;

    const int K0 = in_sizes[1] / OUT_H;   // vertical taps
    const int K1 = in_sizes[3] / OUT_W;   // horizontal taps

    if (K0 == K1) {
        dim3 grid(OUT_H / (2 * G), BC);   // 32 x 24 = 768 blocks, single wave
        switch (K0) {
        case 6:  fused_stream_kernel< 6><<<grid, 256>>>(x, w0, fov0, w1, fov1, out); return;
        case 7:  fused_stream_kernel< 7><<<grid, 256>>>(x, w0, fov0, w1, fov1, out); return;
        case 8:  fused_stream_kernel< 8><<<grid, 256>>>(x, w0, fov0, w1, fov1, out); return;
        case 9:  fused_stream_kernel< 9><<<grid, 256>>>(x, w0, fov0, w1, fov1, out); return;
        case 10: fused_stream_kernel<10><<<grid, 256>>>(x, w0, fov0, w1, fov1, out); return;
        case 11: fused_stream_kernel<11><<<grid, 256>>>(x, w0, fov0, w1, fov1, out); return;
        case 12: fused_stream_kernel<12><<<grid, 256>>>(x, w0, fov0, w1, fov1, out); return;
        default: break;
        }
    }
    dim3 ggrid(OUT_H / G, BC);
    fused_generic_kernel<<<ggrid, 256>>>(x, w0, fov0, w1, fov1, out, K0, K1);
}

// round 10
// speedup vs baseline: 1.2244x; 1.2244x over previous
#include <cuda_runtime.h>
#include <cstdint>

// x (8,3,1024,1024) f32 -> out (8,3,512,512) f32
// d_in: [0]=x, [1]=w0 (K0*512), [2]=fov0 (K0*512 i32)  -> dim2 (H, vertical)
//       [3]=w1 (K1*512), [4]=fov1 (K1*512 i32)         -> dim3 (W, horizontal)
//
// R10: warp-specialized producer/consumer pipeline.
//   warps 0-3 (producers): vertical resample (LDG -> FMA -> STS) into a
//     2-slot ring of 4-row tiles, looping over tiles continuously -> DRAM
//     requests flow the whole kernel (fixes the ~39% bursty DRAM duty cycle
//     of the barrier-phased R5-R9 kernels).
//   warps 4-7 (consumers): horizontal resample from the ring via aligned
//     LDS.128 fast path (regularity-verified), scalar-gather fallback at
//     mirror boundaries.
//   Sync: named barriers, full(1+slot)/empty(3+slot), 128 arrive + 128 sync.

#define BC     24
#define IN_H   1024
#define IN_W   1024
#define OUT_H  512
#define OUT_W  512
#define G      4            // output rows per tile slot
#define PADL   8
#define PADR   8
#define TROW   (PADL + IN_W + PADR)   // 1040 floats
#define RB     2            // ring depth (static smem <= 48KB)
#define NBLK   592          // 148 SMs * 4 blocks

__device__ __forceinline__ void bar_sync(int id) {
    asm volatile("bar.sync %0, 256;" :: "r"(id) : "memory");
}
__device__ __forceinline__ void bar_arrive(int id) {
    asm volatile("bar.arrive %0, 256;" :: "r"(id) : "memory");
}

// ---------------------------------------------------------------------------
// Consumer loop: O = (s1 & 3) compile-time. Contains the whole tile loop so
// all 128 consumer threads hit the named barriers uniformly.
template<int K, int O>
__device__ __forceinline__
void consumer_loop(float (*slots)[G][TROW],
                   const float* __restrict__ w1,
                   const int*   __restrict__ fov1,
                   float*       __restrict__ out,
                   const float* wh, int s1, int tc, int hok)
{
    const int NT  = BC * (OUT_H / G);
    const int ow0 = 4 * tc;
    const int wstart = (s1 + 8 * tc) >> 2;      // floor, may be negative (pad)

    int ln = 0;
    for (int tn = blockIdx.x; tn < NT; tn += gridDim.x, ++ln) {
        const int slot = ln & (RB - 1);
        bar_sync(1 + slot);                      // wait FULL

        const int bc  = tn / (OUT_H / G);
        const int oh0 = (tn % (OUT_H / G)) * G;
        float* outp = out + ((size_t)bc * OUT_H + oh0) * OUT_W + ow0;

        if (hok) {
            constexpr int NQ = (K + 12) / 4;     // covers rel idx O+6+K-1
#pragma unroll
            for (int i = 0; i < G; ++i) {
                const float4* rp =
                    reinterpret_cast<const float4*>(&slots[slot][i][PADL]) + wstart;
                float r[NQ * 4];
#pragma unroll
                for (int q = 0; q < NQ; ++q) {
                    const float4 v = rp[q];
                    r[4*q] = v.x; r[4*q+1] = v.y; r[4*q+2] = v.z; r[4*q+3] = v.w;
                }
                float a0 = 0.f, a1 = 0.f, a2 = 0.f, a3 = 0.f;
#pragma unroll
                for (int j = 0; j < K; ++j) {
                    a0 += wh[j] * r[O + j];
                    a1 += wh[j] * r[O + 2 + j];
                    a2 += wh[j] * r[O + 4 + j];
                    a3 += wh[j] * r[O + 6 + j];
                }
                float4 res; res.x = a0; res.y = a1; res.z = a2; res.w = a3;
                *reinterpret_cast<float4*>(outp + (size_t)i * OUT_W) = res;
            }
        } else {
            for (int i = 0; i < G; ++i) {
                float b0 = 0.f, b1 = 0.f, b2 = 0.f, b3 = 0.f;
                for (int j = 0; j < K; ++j) {
                    const float* sr = slots[slot][i] + PADL;
                    b0 += w1[j*OUT_W+ow0+0] * sr[fov1[j*OUT_W+ow0+0]];
                    b1 += w1[j*OUT_W+ow0+1] * sr[fov1[j*OUT_W+ow0+1]];
                    b2 += w1[j*OUT_W+ow0+2] * sr[fov1[j*OUT_W+ow0+2]];
                    b3 += w1[j*OUT_W+ow0+3] * sr[fov1[j*OUT_W+ow0+3]];
                }
                float4 res; res.x = b0; res.y = b1; res.z = b2; res.w = b3;
                *reinterpret_cast<float4*>(outp + (size_t)i * OUT_W) = res;
            }
        }
        bar_arrive(3 + slot);                    // signal EMPTY
    }
}

// ---------------------------------------------------------------------------
template<int K>
__global__ __launch_bounds__(256, 4)
void fused_ws_kernel(const float* __restrict__ x,
                     const float* __restrict__ w0,
                     const int*   __restrict__ fov0,
                     const float* __restrict__ w1,
                     const int*   __restrict__ fov1,
                     float*       __restrict__ out)
{
    __shared__ __align__(16) float slots[RB][G][TROW];   // 33.3 KB

    const int t  = threadIdx.x;
    const int NT = BC * (OUT_H / G);                     // 3072 tiles

    if (t < 128) {
        // ============================ PRODUCERS ============================
        const int tp   = t;
        const int lane = t & 31;
        constexpr int NROWS = K + 2 * (G - 1);           // 14 for K=8

        int ln = 0;
        for (int tn = blockIdx.x; tn < NT; tn += gridDim.x, ++ln) {
            const int slot = ln & (RB - 1);
            if (ln >= RB) bar_sync(3 + slot);            // wait EMPTY

            const int bc  = tn / (OUT_H / G);
            const int oh0 = (tn % (OUT_H / G)) * G;
            const float4* xb =
                reinterpret_cast<const float4*>(x) + (size_t)bc * (IN_H * IN_W / 4);

            // regularity: fov0[j][oh0+i] == start + 2i + j, w0 oh-invariant
            const int start = fov0[oh0];
            int flag = 1;
            for (int e = lane; e < K * G; e += 32) {
                const int j = e / G, i = e % G, oh = oh0 + i;
                flag &= (fov0[j * OUT_H + oh] == start + 2 * i + j);
                flag &= (w0  [j * OUT_H + oh] == w0[j * OUT_H + oh0]);
            }
            const int regular = __all_sync(0xffffffffu, flag);

            if (regular) {
                float wv[K];
#pragma unroll
                for (int j = 0; j < K; ++j) wv[j] = w0[j * OUT_H + oh0];

#pragma unroll
                for (int h = 0; h < 2; ++h) {
                    const int col = tp + (h << 7);       // float4 column
                    float4 acc[G];
#pragma unroll
                    for (int m = 0; m < NROWS; ++m) {
                        const float4 v = xb[(size_t)(start + m) * (IN_W / 4) + col];
#pragma unroll
                        for (int i = 0; i < G; ++i) {
                            const int j = m - 2 * i;
                            if (j == 0) {                // lazy init
                                acc[i].x = wv[0] * v.x;
                                acc[i].y = wv[0] * v.y;
                                acc[i].z = wv[0] * v.z;
                                acc[i].w = wv[0] * v.w;
                            } else if (j > 0 && j < K) {
                                acc[i].x += wv[j] * v.x;
                                acc[i].y += wv[j] * v.y;
                                acc[i].z += wv[j] * v.z;
                                acc[i].w += wv[j] * v.w;
                            }
                        }
                        if (m >= K - 1 && ((m - (K - 1)) & 1) == 0) {
                            const int i = (m - (K - 1)) >> 1;   // retire
                            *reinterpret_cast<float4*>(
                                &slots[slot][i][PADL + 4 * col]) = acc[i];
                        }
                    }
                }
            } else {
                // mirror-boundary tile: generic gather
                for (int i = 0; i < G; ++i) {
                    const int oh = oh0 + i;
#pragma unroll
                    for (int h = 0; h < 2; ++h) {
                        const int col = tp + (h << 7);
                        float ax = 0.f, ay = 0.f, az = 0.f, aw = 0.f;
                        for (int j = 0; j < K; ++j) {
                            const int   r = fov0[j * OUT_H + oh];
                            const float w = w0  [j * OUT_H + oh];
                            const float4 v = xb[(size_t)r * (IN_W / 4) + col];
                            ax += w * v.x; ay += w * v.y;
                            az += w * v.z; aw += w * v.w;
                        }
                        float4 r4; r4.x = ax; r4.y = ay; r4.z = az; r4.w = aw;
                        *reinterpret_cast<float4*>(
                            &slots[slot][i][PADL + 4 * col]) = r4;
                    }
                }
            }
            __threadfence_block();
            bar_arrive(1 + slot);                        // signal FULL
        }
    } else {
        // ============================ CONSUMERS ============================
        const int tc  = t - 128;
        const int ow0 = 4 * tc;
        const int s1  = fov1[256] - 512;                 // interior reference

        float wh[K];
#pragma unroll
        for (int j = 0; j < K; ++j) wh[j] = w1[j * OUT_W + 256];

        int hok = 1;
#pragma unroll
        for (int j = 0; j < K; ++j) {
            const int4   fv  = *reinterpret_cast<const int4*>(fov1 + j * OUT_W + ow0);
            const float4 wv4 = *reinterpret_cast<const float4*>(w1  + j * OUT_W + ow0);
            const int b = s1 + 2 * ow0 + j;
            hok &= (fv.x == b) & (fv.y == b + 2) & (fv.z == b + 4) & (fv.w == b + 6);
            hok &= (wv4.x == wh[j]) & (wv4.y == wh[j]) &
                   (wv4.z == wh[j]) & (wv4.w == wh[j]);
        }

        const int o = s1 & 3;                            // uniform across grid
        if      (o == 0) consumer_loop<K, 0>(slots, w1, fov1, out, wh, s1, tc, hok);
        else if (o == 1) consumer_loop<K, 1>(slots, w1, fov1, out, wh, s1, tc, hok);
        else if (o == 2) consumer_loop<K, 2>(slots, w1, fov1, out, wh, s1, tc, hok);
        else             consumer_loop<K, 3>(slots, w1, fov1, out, wh, s1, tc, hok);
    }
}

// ---------------------------------------------------------------------------
// Fully generic fallback (runtime K0/K1), parity-split tile (R4 structure).
#define GEN_G 8
__global__ __launch_bounds__(256)
void fused_generic_kernel(const float* __restrict__ x,
                          const float* __restrict__ w0,
                          const int*   __restrict__ fov0,
                          const float* __restrict__ w1,
                          const int*   __restrict__ fov1,
                          float*       __restrict__ out,
                          int K0, int K1)
{
    __shared__ float tile[GEN_G][IN_W];
    const int t   = threadIdx.x;
    const int bc  = blockIdx.y;
    const int oh0 = blockIdx.x * GEN_G;
    const float4* xb = reinterpret_cast<const float4*>(x + (size_t)bc * IN_H * IN_W);

    for (int i = 0; i < GEN_G; ++i) {
        const int oh = oh0 + i;
        float ax = 0.f, ay = 0.f, az = 0.f, aw = 0.f;
        for (int j = 0; j < K0; ++j) {
            const int   r = fov0[j * OUT_H + oh];
            const float w = w0  [j * OUT_H + oh];
            const float4 v = xb[(size_t)r * (IN_W / 4) + t];
            ax += w * v.x; ay += w * v.y; az += w * v.z; aw += w * v.w;
        }
        float2 e; e.x = ax; e.y = az;
        float2 od; od.x = ay; od.y = aw;
        reinterpret_cast<float2*>(tile[i])[t]       = e;
        reinterpret_cast<float2*>(tile[i] + 512)[t] = od;
    }
    __syncthreads();

    float a0[GEN_G], a1[GEN_G];
#pragma unroll
    for (int i = 0; i < GEN_G; ++i) { a0[i] = 0.f; a1[i] = 0.f; }
    for (int j = 0; j < K1; ++j) {
        const float w_a = w1  [j * OUT_W + t];
        const float w_b = w1  [j * OUT_W + t + 256];
        const int   f_a = fov1[j * OUT_W + t];
        const int   f_b = fov1[j * OUT_W + t + 256];
        const int p_a = (f_a >> 1) + ((f_a & 1) << 9);
        const int p_b = (f_b >> 1) + ((f_b & 1) << 9);
#pragma unroll
        for (int i = 0; i < GEN_G; ++i) {
            a0[i] += w_a * tile[i][p_a];
            a1[i] += w_b * tile[i][p_b];
        }
    }
#pragma unroll
    for (int i = 0; i < GEN_G; ++i) {
        float* orow = out + ((size_t)bc * OUT_H + oh0 + i) * OUT_W;
        orow[t]       = a0[i];
        orow[t + 256] = a1[i];
    }
}

// ---------------------------------------------------------------------------

extern "C" void kernel_launch(void* const* d_in, const int* in_sizes, int n_in,
                              void* d_out, int out_size)
{
    const float* x    = (const float*)d_in[0];
    const float* w0   = (const float*)d_in[1];
    const int*   fov0 = (const int*)  d_in[2];
    const float* w1   = (const float*)d_in[3];
    const int*   fov1 = (const int*)  d_in[4];
    float*       out  = (float*)d_out;

    const int K0 = in_sizes[1] / OUT_H;   // vertical taps
    const int K1 = in_sizes[3] / OUT_W;   // horizontal taps

    if (K0 == K1) {
        switch (K0) {
        case 6:  fused_ws_kernel< 6><<<NBLK, 256>>>(x, w0, fov0, w1, fov1, out); return;
        case 7:  fused_ws_kernel< 7><<<NBLK, 256>>>(x, w0, fov0, w1, fov1, out); return;
        case 8:  fused_ws_kernel< 8><<<NBLK, 256>>>(x, w0, fov0, w1, fov1, out); return;
        case 9:  fused_ws_kernel< 9><<<NBLK, 256>>>(x, w0, fov0, w1, fov1, out); return;
        case 10: fused_ws_kernel<10><<<NBLK, 256>>>(x, w0, fov0, w1, fov1, out); return;
        case 11: fused_ws_kernel<11><<<NBLK, 256>>>(x, w0, fov0, w1, fov1, out); return;
        case 12: fused_ws_kernel<12><<<NBLK, 256>>>(x, w0, fov0, w1, fov1, out); return;
        default: break;
        }
    }
    dim3 ggrid(OUT_H / GEN_G, BC);
    fused_generic_kernel<<<ggrid, 256>>>(x, w0, fov0, w1, fov1, out, K0, K1);
}

// round 11
// speedup vs baseline: 1.3096x; 1.0696x over previous
#include <cuda_runtime.h>
#include <cstdint>

// x (8,3,1024,1024) f32 -> out (8,3,512,512) f32
// d_in: [0]=x, [1]=w0 (K0*512), [2]=fov0 (K0*512 i32)  -> dim2 (H, vertical)
//       [3]=w1 (K1*512), [4]=fov1 (K1*512 i32)         -> dim3 (W, horizontal)
//
// R11: R8 structure (streaming vertical pass with REGISTER weights,
// LDS.128-fast horizontal pass), single clean change: 6 blocks/SM.
//   - lazy accumulator init (acc[i] first written at tap j==0) keeps only
//     <=4 accumulators live -> regs 48 -> 40 (validated in R9, same rel_err)
//   - __launch_bounds__(256, 6)
// Grid stays (64, 24) = 1536 blocks. 6 blk/SM: 61.4K regs, 204KB smem. This
// isolates the occupancy/phase-convoy hypothesis that R7 (smem-weight LDS
// poison) and R9 (persistent-grid poison) never tested cleanly.

#define BC     24
#define IN_H   1024
#define IN_W   1024
#define OUT_H  512
#define OUT_W  512
#define G      8            // output rows per block
#define PADW   16           // tile row padding (floats) on each side
#define TROW   (IN_W + 2 * PADW)

// ---------------------------------------------------------------------------
// Fast horizontal rows: O = (s1 & 3), compile-time. Each thread produces
// outputs (ow0, ow0+1) for all G rows from NQ aligned float4 smem loads.
template<int K, int O>
__device__ __forceinline__
void hfast_rows(const float tile[G][TROW], int wstart,
                const float* __restrict__ wh,
                float* __restrict__ outp /* &out[bc][oh0][ow0] */)
{
    constexpr int NQ = (K + 8) / 4;       // float4 loads covering idx O+K+1
#pragma unroll
    for (int i = 0; i < G; ++i) {
        const float4* rp = reinterpret_cast<const float4*>(tile[i] + PADW) + wstart;
        float r[NQ * 4];
#pragma unroll
        for (int q = 0; q < NQ; ++q) {
            const float4 v = rp[q];
            r[4 * q + 0] = v.x; r[4 * q + 1] = v.y;
            r[4 * q + 2] = v.z; r[4 * q + 3] = v.w;
        }
        float a0 = 0.f, a1 = 0.f;
#pragma unroll
        for (int j = 0; j < K; ++j) {
            a0 += wh[j] * r[O + j];
            a1 += wh[j] * r[O + 2 + j];
        }
        float2 res; res.x = a0; res.y = a1;
        *reinterpret_cast<float2*>(outp + (size_t)i * OUT_W) = res;
    }
}

// ---------------------------------------------------------------------------
template<int K>
__global__ __launch_bounds__(256, 6)
void fused_stream_kernel(const float* __restrict__ x,
                         const float* __restrict__ w0,
                         const int*   __restrict__ fov0,
                         const float* __restrict__ w1,
                         const int*   __restrict__ fov1,
                         float*       __restrict__ out)
{
    __shared__ float tile[G][TROW];              // ~33 KB, plain + padded

    const int t   = threadIdx.x;                 // 0..255
    const int bc  = blockIdx.y;
    const int oh0 = blockIdx.x * G;

    const float4* xb = reinterpret_cast<const float4*>(x + (size_t)bc * IN_H * IN_W);

    // ---- vertical regularity: fov0[j][oh0+i] == start + 2i + j, w0 oh-invar.
    const int start = fov0[oh0];
    int flag = 1;
    if (t < K * G) {
        const int j  = t / G;
        const int i  = t % G;
        const int oh = oh0 + i;
        flag  = (fov0[j * OUT_H + oh] == start + 2 * i + j);
        flag &= (w0  [j * OUT_H + oh] == w0[j * OUT_H + oh0]);
    }
    const int regular = __syncthreads_and(flag);

    if (regular) {
        // ---------- Phase 1a: stream K+2(G-1) rows into G accumulators ------
        constexpr int NROWS = K + 2 * (G - 1);   // 22 for K=8

        float wv[K];
#pragma unroll
        for (int j = 0; j < K; ++j) wv[j] = w0[j * OUT_H + oh0];

        float4 acc[G];
#pragma unroll
        for (int m = 0; m < NROWS; ++m) {
            const float4 v = xb[(size_t)(start + m) * (IN_W / 4) + t];
#pragma unroll
            for (int i = 0; i < G; ++i) {
                const int j = m - 2 * i;
                if (j == 0) {                    // lazy init: short live range
                    acc[i].x = wv[0] * v.x;
                    acc[i].y = wv[0] * v.y;
                    acc[i].z = wv[0] * v.z;
                    acc[i].w = wv[0] * v.w;
                } else if (j > 0 && j < K) {
                    acc[i].x += wv[j] * v.x;
                    acc[i].y += wv[j] * v.y;
                    acc[i].z += wv[j] * v.z;
                    acc[i].w += wv[j] * v.w;
                }
            }
            if (m >= K - 1 && ((m - (K - 1)) & 1) == 0) {
                const int i = (m - (K - 1)) / 2; // retire closed window
                reinterpret_cast<float4*>(tile[i] + PADW)[t] = acc[i];
            }
        }
    } else {
        // ---------- Phase 1b: generic gather (boundary blocks) ----------
        for (int i = 0; i < G; ++i) {
            const int oh = oh0 + i;
            float ax = 0.f, ay = 0.f, az = 0.f, aw = 0.f;
            for (int j = 0; j < K; ++j) {
                const int   r = fov0[j * OUT_H + oh];
                const float w = w0  [j * OUT_H + oh];
                const float4 v = xb[(size_t)r * (IN_W / 4) + t];
                ax += w * v.x; ay += w * v.y; az += w * v.z; aw += w * v.w;
            }
            float4 r4; r4.x = ax; r4.y = ay; r4.z = az; r4.w = aw;
            reinterpret_cast<float4*>(tile[i] + PADW)[t] = r4;
        }
    }
    __syncthreads();

    // ---------------- Phase 2: horizontal resample ---------------------------
    const int ow0 = 2 * t;
    const int s1  = fov1[256] - 512;             // reference interior column

    float wh[K];
#pragma unroll
    for (int j = 0; j < K; ++j) wh[j] = w1[j * OUT_W + 256];

    int ok = 1;
#pragma unroll
    for (int j = 0; j < K; ++j) {
        const int2   fv = *reinterpret_cast<const int2*>(fov1 + j * OUT_W + ow0);
        const float2 wv = *reinterpret_cast<const float2*>(w1  + j * OUT_W + ow0);
        ok &= (fv.x == s1 + 2 * ow0 + j) & (fv.y == s1 + 2 * ow0 + 2 + j);
        ok &= (wv.x == wh[j]) & (wv.y == wh[j]);
    }

    float* outp = out + ((size_t)bc * OUT_H + oh0) * OUT_W + ow0;

    if (ok) {
        const int o      = s1 & 3;               // uniform across entire grid
        const int wstart = (s1 + 4 * t) >> 2;    // aligned float4 index
        if      (o == 0) hfast_rows<K, 0>(tile, wstart, wh, outp);
        else if (o == 1) hfast_rows<K, 1>(tile, wstart, wh, outp);
        else if (o == 2) hfast_rows<K, 2>(tile, wstart, wh, outp);
        else             hfast_rows<K, 3>(tile, wstart, wh, outp);
    } else {
        for (int i = 0; i < G; ++i) {
            float b0 = 0.f, b1 = 0.f;
            for (int j = 0; j < K; ++j) {
                b0 += w1[j * OUT_W + ow0]     * tile[i][PADW + fov1[j * OUT_W + ow0]];
                b1 += w1[j * OUT_W + ow0 + 1] * tile[i][PADW + fov1[j * OUT_W + ow0 + 1]];
            }
            float2 res; res.x = b0; res.y = b1;
            *reinterpret_cast<float2*>(outp + (size_t)i * OUT_W) = res;
        }
    }
}

// ---------------------------------------------------------------------------
// Fully generic fallback (runtime K0/K1), parity-split tile.
__global__ __launch_bounds__(256)
void fused_generic_kernel(const float* __restrict__ x,
                          const float* __restrict__ w0,
                          const int*   __restrict__ fov0,
                          const float* __restrict__ w1,
                          const int*   __restrict__ fov1,
                          float*       __restrict__ out,
                          int K0, int K1)
{
    __shared__ float tile[G][IN_W];
    const int t   = threadIdx.x;
    const int bc  = blockIdx.y;
    const int oh0 = blockIdx.x * G;
    const float4* xb = reinterpret_cast<const float4*>(x + (size_t)bc * IN_H * IN_W);

    for (int i = 0; i < G; ++i) {
        const int oh = oh0 + i;
        float ax = 0.f, ay = 0.f, az = 0.f, aw = 0.f;
        for (int j = 0; j < K0; ++j) {
            const int   r = fov0[j * OUT_H + oh];
            const float w = w0  [j * OUT_H + oh];
            const float4 v = xb[(size_t)r * (IN_W / 4) + t];
            ax += w * v.x; ay += w * v.y; az += w * v.z; aw += w * v.w;
        }
        float2 e; e.x = ax; e.y = az;
        float2 o; o.x = ay; o.y = aw;
        reinterpret_cast<float2*>(tile[i])[t]       = e;
        reinterpret_cast<float2*>(tile[i] + 512)[t] = o;
    }
    __syncthreads();

    float a0[G], a1[G];
#pragma unroll
    for (int i = 0; i < G; ++i) { a0[i] = 0.f; a1[i] = 0.f; }
    for (int j = 0; j < K1; ++j) {
        const float w_a = w1  [j * OUT_W + t];
        const float w_b = w1  [j * OUT_W + t + 256];
        const int   f_a = fov1[j * OUT_W + t];
        const int   f_b = fov1[j * OUT_W + t + 256];
        const int p_a = (f_a >> 1) + ((f_a & 1) << 9);
        const int p_b = (f_b >> 1) + ((f_b & 1) << 9);
#pragma unroll
        for (int i = 0; i < G; ++i) {
            a0[i] += w_a * tile[i][p_a];
            a1[i] += w_b * tile[i][p_b];
        }
    }
#pragma unroll
    for (int i = 0; i < G; ++i) {
        float* orow = out + ((size_t)bc * OUT_H + oh0 + i) * OUT_W;
        orow[t]       = a0[i];
        orow[t + 256] = a1[i];
    }
}

// ---------------------------------------------------------------------------

extern "C" void kernel_launch(void* const* d_in, const int* in_sizes, int n_in,
                              void* d_out, int out_size)
{
    const float* x    = (const float*)d_in[0];
    const float* w0   = (const float*)d_in[1];
    const int*   fov0 = (const int*)  d_in[2];
    const float* w1   = (const float*)d_in[3];
    const int*   fov1 = (const int*)  d_in[4];
    float*       out  = (float*)d_out;

    const int K0 = in_sizes[1] / OUT_H;   // vertical taps
    const int K1 = in_sizes[3] / OUT_W;   // horizontal taps

    dim3 grid(OUT_H / G, BC);

    if (K0 == K1) {
        switch (K0) {
        case 6:  fused_stream_kernel< 6><<<grid, 256>>>(x, w0, fov0, w1, fov1, out); return;
        case 7:  fused_stream_kernel< 7><<<grid, 256>>>(x, w0, fov0, w1, fov1, out); return;
        case 8:  fused_stream_kernel< 8><<<grid, 256>>>(x, w0, fov0, w1, fov1, out); return;
        case 9:  fused_stream_kernel< 9><<<grid, 256>>>(x, w0, fov0, w1, fov1, out); return;
        case 10: fused_stream_kernel<10><<<grid, 256>>>(x, w0, fov0, w1, fov1, out); return;
        case 11: fused_stream_kernel<11><<<grid, 256>>>(x, w0, fov0, w1, fov1, out); return;
        case 12: fused_stream_kernel<12><<<grid, 256>>>(x, w0, fov0, w1, fov1, out); return;
        default: break;
        }
    }
    fused_generic_kernel<<<grid, 256>>>(x, w0, fov0, w1, fov1, out, K0, K1);
}